// round 1
// baseline (speedup 1.0000x reference)
#include <cuda_runtime.h>
#include <cstdint>

// ---------------------------------------------------------------------------
// SelfAttention: O = softmax( relu(XWq+bq) @ relu(XWk+bk)^T ) @ relu(XWv+bv)
// B=8, T=2048, D=DK=DV=1024, fp32 in/out.
// Strategy: tf32 mma.sync GEMMs (rna-rounded), materialized scores, fp32 softmax.
// ---------------------------------------------------------------------------

#define BATCH 8
#define SEQ   2048
#define DIM   1024

// Scratch (device globals; no allocations allowed)
__device__ __align__(256) float g_Q[(size_t)BATCH * SEQ * DIM];
__device__ __align__(256) float g_K[(size_t)BATCH * SEQ * DIM];
__device__ __align__(256) float g_V[(size_t)BATCH * SEQ * DIM];
__device__ __align__(256) float g_S[(size_t)BATCH * SEQ * SEQ];

__device__ __forceinline__ uint32_t f2tf32(float x) {
    uint32_t y;
    asm("cvt.rna.tf32.f32 %0, %1;" : "=r"(y) : "f"(x));
    return y;
}

__device__ __forceinline__ void mma_tf32(float c[4], const uint32_t a[4], const uint32_t b[2]) {
    asm volatile(
        "mma.sync.aligned.m16n8k8.row.col.f32.tf32.tf32.f32 "
        "{%0,%1,%2,%3}, {%4,%5,%6,%7}, {%8,%9}, {%0,%1,%2,%3};"
        : "+f"(c[0]), "+f"(c[1]), "+f"(c[2]), "+f"(c[3])
        : "r"(a[0]), "r"(a[1]), "r"(a[2]), "r"(a[3]), "r"(b[0]), "r"(b[1]));
}

// ---------------------------------------------------------------------------
// Generic tiled tf32 GEMM:
//   TRANS_B = false:  C[M,N] = A[M,K] @ B[K,N]          (B row-major [K,N])
//   TRANS_B = true :  C[M,N] = A[M,K] @ B[N,K]^T        (B row-major [N,K])
//   BIAS_RELU: C = relu(C + bias[n])
// Block 128x128x32, 256 threads, warp tile 32x64.
// Batched via blockIdx.z with element strides.
// ---------------------------------------------------------------------------
template <bool TRANS_B, bool BIAS_RELU>
__global__ __launch_bounds__(256)
void gemm_tf32_kernel(const float* __restrict__ A, const float* __restrict__ Bm,
                      const float* __restrict__ bias, float* __restrict__ C,
                      int M, int N, int K,
                      size_t strideA, size_t strideB, size_t strideC)
{
    constexpr int BM = 128, BN = 128, BK = 32;
    constexpr int AST = 36;   // As[row][k] stride (pad 4) -> conflict-free frag loads
    constexpr int BST_NT = 36;   // Bs[n][k]
    constexpr int BST_NN = 132;  // Bs[k][n] (pad 4)

    A  += (size_t)blockIdx.z * strideA;
    Bm += (size_t)blockIdx.z * strideB;
    C  += (size_t)blockIdx.z * strideC;

    __shared__ __align__(16) uint32_t As[BM * AST];
    __shared__ __align__(16) uint32_t Bs[TRANS_B ? (BN * BST_NT) : (BK * BST_NN)];

    const int tid  = threadIdx.x;
    const int lane = tid & 31;
    const int warp = tid >> 5;
    const int wm0  = (warp >> 1) * 32;   // warp tile m origin within block (4 warps in m)
    const int wn0  = (warp & 1) * 64;    // 2 warps in n

    const int blockM = blockIdx.y * BM;
    const int blockN = blockIdx.x * BN;

    const int qr = lane >> 2;  // 0..7
    const int qc = lane & 3;   // 0..3

    float acc[2][8][4];
    #pragma unroll
    for (int i = 0; i < 2; i++)
        #pragma unroll
        for (int j = 0; j < 8; j++)
            #pragma unroll
            for (int v = 0; v < 4; v++) acc[i][j][v] = 0.0f;

    for (int k0 = 0; k0 < K; k0 += BK) {
        // ---- load A tile [BM x BK] ----
        {
            const float* Ag = A + (size_t)blockM * K + k0;
            #pragma unroll
            for (int p = 0; p < 4; p++) {
                int f   = tid + p * 256;        // 1024 float4 total
                int row = f >> 3;               // 8 float4 per row
                int c4  = f & 7;
                float4 t = *reinterpret_cast<const float4*>(Ag + (size_t)row * K + c4 * 4);
                uint4 u;
                u.x = f2tf32(t.x); u.y = f2tf32(t.y); u.z = f2tf32(t.z); u.w = f2tf32(t.w);
                *reinterpret_cast<uint4*>(&As[row * AST + c4 * 4]) = u;
            }
        }
        // ---- load B tile ----
        if (TRANS_B) {
            // Bm is [N,K]; smem Bs[n][k]
            const float* Bg = Bm + (size_t)blockN * K + k0;
            #pragma unroll
            for (int p = 0; p < 4; p++) {
                int f   = tid + p * 256;
                int row = f >> 3;               // n
                int c4  = f & 7;                // k/4
                float4 t = *reinterpret_cast<const float4*>(Bg + (size_t)row * K + c4 * 4);
                uint4 u;
                u.x = f2tf32(t.x); u.y = f2tf32(t.y); u.z = f2tf32(t.z); u.w = f2tf32(t.w);
                *reinterpret_cast<uint4*>(&Bs[row * BST_NT + c4 * 4]) = u;
            }
        } else {
            // Bm is [K,N]; smem Bs[k][n]
            const float* Bg = Bm + (size_t)k0 * N + blockN;
            #pragma unroll
            for (int p = 0; p < 4; p++) {
                int f   = tid + p * 256;
                int row = f >> 5;               // k (32 float4 per row)
                int c4  = f & 31;               // n/4
                float4 t = *reinterpret_cast<const float4*>(Bg + (size_t)row * N + c4 * 4);
                uint4 u;
                u.x = f2tf32(t.x); u.y = f2tf32(t.y); u.z = f2tf32(t.z); u.w = f2tf32(t.w);
                *reinterpret_cast<uint4*>(&Bs[row * BST_NN + c4 * 4]) = u;
            }
        }
        __syncthreads();

        // ---- compute: 4 k-steps of m16n8k8 ----
        #pragma unroll
        for (int kk = 0; kk < BK; kk += 8) {
            uint32_t a[2][4];
            #pragma unroll
            for (int mt = 0; mt < 2; mt++) {
                int r0 = wm0 + mt * 16 + qr;
                a[mt][0] = As[r0 * AST + kk + qc];
                a[mt][1] = As[(r0 + 8) * AST + kk + qc];
                a[mt][2] = As[r0 * AST + kk + qc + 4];
                a[mt][3] = As[(r0 + 8) * AST + kk + qc + 4];
            }
            uint32_t b[8][2];
            #pragma unroll
            for (int nt = 0; nt < 8; nt++) {
                if (TRANS_B) {
                    int n = wn0 + nt * 8 + qr;
                    b[nt][0] = Bs[n * BST_NT + kk + qc];
                    b[nt][1] = Bs[n * BST_NT + kk + qc + 4];
                } else {
                    int n = wn0 + nt * 8 + qr;
                    b[nt][0] = Bs[(kk + qc) * BST_NN + n];
                    b[nt][1] = Bs[(kk + qc + 4) * BST_NN + n];
                }
            }
            #pragma unroll
            for (int mt = 0; mt < 2; mt++)
                #pragma unroll
                for (int nt = 0; nt < 8; nt++)
                    mma_tf32(acc[mt][nt], a[mt], b[nt]);
        }
        __syncthreads();
    }

    // ---- epilogue ----
    #pragma unroll
    for (int mt = 0; mt < 2; mt++) {
        #pragma unroll
        for (int nt = 0; nt < 8; nt++) {
            int gm = blockM + wm0 + mt * 16 + qr;
            int gn = blockN + wn0 + nt * 8 + qc * 2;
            float2 v0, v1;
            v0.x = acc[mt][nt][0]; v0.y = acc[mt][nt][1];
            v1.x = acc[mt][nt][2]; v1.y = acc[mt][nt][3];
            if (BIAS_RELU) {
                float2 bb = *reinterpret_cast<const float2*>(&bias[gn]);
                v0.x = fmaxf(v0.x + bb.x, 0.0f);
                v0.y = fmaxf(v0.y + bb.y, 0.0f);
                v1.x = fmaxf(v1.x + bb.x, 0.0f);
                v1.y = fmaxf(v1.y + bb.y, 0.0f);
            }
            *reinterpret_cast<float2*>(&C[(size_t)gm * N + gn]) = v0;
            *reinterpret_cast<float2*>(&C[(size_t)(gm + 8) * N + gn]) = v1;
        }
    }
}

// ---------------------------------------------------------------------------
// Row softmax over S rows of length 2048. One block (256 threads) per row.
// ---------------------------------------------------------------------------
__global__ __launch_bounds__(256)
void softmax_kernel(float* __restrict__ S, int ncols)
{
    const size_t row = blockIdx.x;
    float* p = S + row * (size_t)ncols;
    const int tid  = threadIdx.x;
    const int lane = tid & 31;
    const int warp = tid >> 5;

    __shared__ float red[8];

    float v[8];
    float m = -1e30f;
    #pragma unroll
    for (int i = 0; i < 8; i++) {
        v[i] = p[tid + i * 256];
        m = fmaxf(m, v[i]);
    }
    #pragma unroll
    for (int o = 16; o; o >>= 1) m = fmaxf(m, __shfl_xor_sync(0xffffffffu, m, o));
    if (lane == 0) red[warp] = m;
    __syncthreads();
    m = red[0];
    #pragma unroll
    for (int i = 1; i < 8; i++) m = fmaxf(m, red[i]);
    __syncthreads();

    float s = 0.0f;
    #pragma unroll
    for (int i = 0; i < 8; i++) {
        v[i] = __expf(v[i] - m);
        s += v[i];
    }
    #pragma unroll
    for (int o = 16; o; o >>= 1) s += __shfl_xor_sync(0xffffffffu, s, o);
    if (lane == 0) red[warp] = s;
    __syncthreads();
    float tot = red[0];
    #pragma unroll
    for (int i = 1; i < 8; i++) tot += red[i];
    float inv = 1.0f / tot;
    #pragma unroll
    for (int i = 0; i < 8; i++) p[tid + i * 256] = v[i] * inv;
}

// ---------------------------------------------------------------------------
// Launch
// ---------------------------------------------------------------------------
extern "C" void kernel_launch(void* const* d_in, const int* in_sizes, int n_in,
                              void* d_out, int out_size)
{
    const float* X  = (const float*)d_in[0];
    const float* Wq = (const float*)d_in[1];
    const float* bq = (const float*)d_in[2];
    const float* Wk = (const float*)d_in[3];
    const float* bk = (const float*)d_in[4];
    const float* Wv = (const float*)d_in[5];
    const float* bv = (const float*)d_in[6];
    float* out = (float*)d_out;

    void *pQ, *pK, *pV, *pS;
    cudaGetSymbolAddress(&pQ, g_Q);
    cudaGetSymbolAddress(&pK, g_K);
    cudaGetSymbolAddress(&pV, g_V);
    cudaGetSymbolAddress(&pS, g_S);
    float* Q = (float*)pQ;
    float* K = (float*)pK;
    float* V = (float*)pV;
    float* S = (float*)pS;

    const int M_qkv = BATCH * SEQ;   // 16384
    dim3 block(256);

    // 1) QKV projections: relu(X @ W + b), NN GEMMs, M=16384 N=1024 K=1024
    {
        dim3 grid(DIM / 128, M_qkv / 128, 1);
        gemm_tf32_kernel<false, true><<<grid, block>>>(X, Wq, bq, Q, M_qkv, DIM, DIM, 0, 0, 0);
        gemm_tf32_kernel<false, true><<<grid, block>>>(X, Wk, bk, K, M_qkv, DIM, DIM, 0, 0, 0);
        gemm_tf32_kernel<false, true><<<grid, block>>>(X, Wv, bv, V, M_qkv, DIM, DIM, 0, 0, 0);
    }

    // 2) scores: S_b = Q_b @ K_b^T, per-batch, M=N=2048 K=1024 (NT)
    {
        dim3 grid(SEQ / 128, SEQ / 128, BATCH);
        gemm_tf32_kernel<true, false><<<grid, block>>>(
            Q, K, nullptr, S, SEQ, SEQ, DIM,
            (size_t)SEQ * DIM, (size_t)SEQ * DIM, (size_t)SEQ * SEQ);
    }

    // 3) softmax over rows of S (B*T rows of length T)
    softmax_kernel<<<BATCH * SEQ, 256>>>(S, SEQ);

    // 4) out: O_b = P_b @ V_b, M=2048 N=1024 K=2048 (NN)
    {
        dim3 grid(DIM / 128, SEQ / 128, BATCH);
        gemm_tf32_kernel<false, false><<<grid, block>>>(
            S, V, nullptr, out, SEQ, DIM, SEQ,
            (size_t)SEQ * SEQ, (size_t)SEQ * DIM, (size_t)SEQ * DIM);
    }
}

// round 2
// speedup vs baseline: 1.0718x; 1.0718x over previous
#include <cuda_runtime.h>
#include <cstdint>

// ---------------------------------------------------------------------------
// SelfAttention: O = softmax( relu(XWq+bq) @ relu(XWk+bk)^T ) @ relu(XWv+bv)
// B=8, T=2048, D=DK=DV=1024, fp32 in/out.
// tf32 mma.sync GEMMs with 3-stage cp.async pipeline; fp32 softmax.
// ---------------------------------------------------------------------------

#define BATCH 8
#define SEQ   2048
#define DIM   1024

// Scratch (device globals; no allocations allowed)
__device__ __align__(256) float g_Q[(size_t)BATCH * SEQ * DIM];
__device__ __align__(256) float g_K[(size_t)BATCH * SEQ * DIM];
__device__ __align__(256) float g_V[(size_t)BATCH * SEQ * DIM];
__device__ __align__(256) float g_S[(size_t)BATCH * SEQ * SEQ];

__device__ __forceinline__ uint32_t f2tf32(float x) {
    uint32_t y;
    asm("cvt.rna.tf32.f32 %0, %1;" : "=r"(y) : "f"(x));
    return y;
}

__device__ __forceinline__ void mma_tf32(float c[4], const uint32_t a[4], const uint32_t b[2]) {
    asm volatile(
        "mma.sync.aligned.m16n8k8.row.col.f32.tf32.tf32.f32 "
        "{%0,%1,%2,%3}, {%4,%5,%6,%7}, {%8,%9}, {%0,%1,%2,%3};"
        : "+f"(c[0]), "+f"(c[1]), "+f"(c[2]), "+f"(c[3])
        : "r"(a[0]), "r"(a[1]), "r"(a[2]), "r"(a[3]), "r"(b[0]), "r"(b[1]));
}

__device__ __forceinline__ void cp_async16(void* smem_dst, const void* gsrc) {
    uint32_t d = (uint32_t)__cvta_generic_to_shared(smem_dst);
    asm volatile("cp.async.cg.shared.global [%0], [%1], 16;\n" :: "r"(d), "l"(gsrc));
}
__device__ __forceinline__ void cp_commit() {
    asm volatile("cp.async.commit_group;\n" ::: "memory");
}
template <int N>
__device__ __forceinline__ void cp_wait() {
    asm volatile("cp.async.wait_group %0;\n" :: "n"(N) : "memory");
}

// ---------------------------------------------------------------------------
// Tiled tf32 GEMM, 3-stage cp.async pipeline.
//   TRANS_B=false: C[M,N] = A[M,K] @ B[K,N]      (B row-major [K,N])
//   TRANS_B=true : C[M,N] = A[M,K] @ B[N,K]^T    (B row-major [N,K])
//   BIAS_RELU: C = relu(C + bias[n])
// Block 128x128x32, 256 threads, warp tile 32x64, batched via blockIdx.z.
// ---------------------------------------------------------------------------
template <bool TRANS_B, bool BIAS_RELU>
__global__ __launch_bounds__(256, 2)
void gemm_tf32_kernel(const float* __restrict__ A, const float* __restrict__ Bm,
                      const float* __restrict__ bias, float* __restrict__ C,
                      int M, int N, int K,
                      size_t strideA, size_t strideB, size_t strideC)
{
    constexpr int BM = 128, BN = 128, BK = 32, STAGES = 3;
    constexpr int AST = 36;                        // As[row][k] stride (pad 4)
    constexpr int BST = TRANS_B ? 36 : 132;        // Bs[n][k] / Bs[k][n]
    constexpr int ASZ = BM * AST;                  // floats per A stage
    constexpr int BSZ = TRANS_B ? (BN * 36) : (BK * 132);

    extern __shared__ float sm[];
    float* As = sm;
    float* Bs = sm + STAGES * ASZ;

    A  += (size_t)blockIdx.z * strideA;
    Bm += (size_t)blockIdx.z * strideB;
    C  += (size_t)blockIdx.z * strideC;

    const int tid  = threadIdx.x;
    const int lane = tid & 31;
    const int warp = tid >> 5;
    const int wm0  = (warp >> 1) * 32;
    const int wn0  = (warp & 1) * 64;

    const int blockM = blockIdx.y * BM;
    const int blockN = blockIdx.x * BN;

    const int qr = lane >> 2;
    const int qc = lane & 3;

    float acc[2][8][4];
    #pragma unroll
    for (int i = 0; i < 2; i++)
        #pragma unroll
        for (int j = 0; j < 8; j++)
            #pragma unroll
            for (int v = 0; v < 4; v++) acc[i][j][v] = 0.0f;

    // ---- async tile loader ----
    auto load_tile = [&](int stage, int k0) {
        float* Asd = As + stage * ASZ;
        const float* Ag = A + (size_t)blockM * K + k0;
        #pragma unroll
        for (int p = 0; p < 4; p++) {
            int f   = tid + p * 256;     // 1024 x 16B for the A tile
            int row = f >> 3;
            int c4  = f & 7;
            cp_async16(Asd + row * AST + c4 * 4, Ag + (size_t)row * K + c4 * 4);
        }
        float* Bsd = Bs + stage * BSZ;
        if (TRANS_B) {
            const float* Bg = Bm + (size_t)blockN * K + k0;
            #pragma unroll
            for (int p = 0; p < 4; p++) {
                int f   = tid + p * 256;
                int row = f >> 3;        // n
                int c4  = f & 7;         // k/4
                cp_async16(Bsd + row * 36 + c4 * 4, Bg + (size_t)row * K + c4 * 4);
            }
        } else {
            const float* Bg = Bm + (size_t)k0 * N + blockN;
            #pragma unroll
            for (int p = 0; p < 4; p++) {
                int f   = tid + p * 256;
                int row = f >> 5;        // k
                int c4  = f & 31;        // n/4
                cp_async16(Bsd + row * 132 + c4 * 4, Bg + (size_t)row * N + c4 * 4);
            }
        }
    };

    const int KT = K / BK;

    // prologue: fill STAGES-1 stages
    load_tile(0, 0);
    cp_commit();
    load_tile(1, BK);
    cp_commit();

    for (int kt = 0; kt < KT; kt++) {
        cp_wait<1>();          // tile kt resident
        __syncthreads();       // visible to all; stage (kt-1)%3 compute done

        if (kt + 2 < KT) load_tile((kt + 2) % STAGES, (kt + 2) * BK);
        cp_commit();

        const float* Asb = As + (kt % STAGES) * ASZ;
        const float* Bsb = Bs + (kt % STAGES) * BSZ;

        #pragma unroll
        for (int kk = 0; kk < BK; kk += 8) {
            uint32_t a[2][4];
            #pragma unroll
            for (int mt = 0; mt < 2; mt++) {
                int r0 = wm0 + mt * 16 + qr;
                a[mt][0] = f2tf32(Asb[r0 * AST + kk + qc]);
                a[mt][1] = f2tf32(Asb[(r0 + 8) * AST + kk + qc]);
                a[mt][2] = f2tf32(Asb[r0 * AST + kk + qc + 4]);
                a[mt][3] = f2tf32(Asb[(r0 + 8) * AST + kk + qc + 4]);
            }
            uint32_t b[8][2];
            #pragma unroll
            for (int nt = 0; nt < 8; nt++) {
                int n = wn0 + nt * 8 + qr;
                if (TRANS_B) {
                    b[nt][0] = f2tf32(Bsb[n * 36 + kk + qc]);
                    b[nt][1] = f2tf32(Bsb[n * 36 + kk + qc + 4]);
                } else {
                    b[nt][0] = f2tf32(Bsb[(kk + qc) * 132 + n]);
                    b[nt][1] = f2tf32(Bsb[(kk + qc + 4) * 132 + n]);
                }
            }
            #pragma unroll
            for (int mt = 0; mt < 2; mt++)
                #pragma unroll
                for (int nt = 0; nt < 8; nt++)
                    mma_tf32(acc[mt][nt], a[mt], b[nt]);
        }
    }

    // ---- epilogue ----
    #pragma unroll
    for (int mt = 0; mt < 2; mt++) {
        #pragma unroll
        for (int nt = 0; nt < 8; nt++) {
            int gm = blockM + wm0 + mt * 16 + qr;
            int gn = blockN + wn0 + nt * 8 + qc * 2;
            float2 v0, v1;
            v0.x = acc[mt][nt][0]; v0.y = acc[mt][nt][1];
            v1.x = acc[mt][nt][2]; v1.y = acc[mt][nt][3];
            if (BIAS_RELU) {
                float2 bb = *reinterpret_cast<const float2*>(&bias[gn]);
                v0.x = fmaxf(v0.x + bb.x, 0.0f);
                v0.y = fmaxf(v0.y + bb.y, 0.0f);
                v1.x = fmaxf(v1.x + bb.x, 0.0f);
                v1.y = fmaxf(v1.y + bb.y, 0.0f);
            }
            *reinterpret_cast<float2*>(&C[(size_t)gm * N + gn]) = v0;
            *reinterpret_cast<float2*>(&C[(size_t)(gm + 8) * N + gn]) = v1;
        }
    }
}

// ---------------------------------------------------------------------------
// Row softmax over rows of length 2048. One block (256 threads) per row.
// ---------------------------------------------------------------------------
__global__ __launch_bounds__(256)
void softmax_kernel(float* __restrict__ S, int ncols)
{
    const size_t row = blockIdx.x;
    float* p = S + row * (size_t)ncols;
    const int tid  = threadIdx.x;
    const int lane = tid & 31;
    const int warp = tid >> 5;

    __shared__ float red[8];

    float v[8];
    float m = -1e30f;
    #pragma unroll
    for (int i = 0; i < 8; i++) {
        v[i] = p[tid + i * 256];
        m = fmaxf(m, v[i]);
    }
    #pragma unroll
    for (int o = 16; o; o >>= 1) m = fmaxf(m, __shfl_xor_sync(0xffffffffu, m, o));
    if (lane == 0) red[warp] = m;
    __syncthreads();
    m = red[0];
    #pragma unroll
    for (int i = 1; i < 8; i++) m = fmaxf(m, red[i]);
    __syncthreads();

    float s = 0.0f;
    #pragma unroll
    for (int i = 0; i < 8; i++) {
        v[i] = __expf(v[i] - m);
        s += v[i];
    }
    #pragma unroll
    for (int o = 16; o; o >>= 1) s += __shfl_xor_sync(0xffffffffu, s, o);
    if (lane == 0) red[warp] = s;
    __syncthreads();
    float tot = red[0];
    #pragma unroll
    for (int i = 1; i < 8; i++) tot += red[i];
    float inv = 1.0f / tot;
    #pragma unroll
    for (int i = 0; i < 8; i++) p[tid + i * 256] = v[i] * inv;
}

// ---------------------------------------------------------------------------
// Launch
// ---------------------------------------------------------------------------
extern "C" void kernel_launch(void* const* d_in, const int* in_sizes, int n_in,
                              void* d_out, int out_size)
{
    const float* X  = (const float*)d_in[0];
    const float* Wq = (const float*)d_in[1];
    const float* bq = (const float*)d_in[2];
    const float* Wk = (const float*)d_in[3];
    const float* bk = (const float*)d_in[4];
    const float* Wv = (const float*)d_in[5];
    const float* bv = (const float*)d_in[6];
    float* out = (float*)d_out;

    void *pQ, *pK, *pV, *pS;
    cudaGetSymbolAddress(&pQ, g_Q);
    cudaGetSymbolAddress(&pK, g_K);
    cudaGetSymbolAddress(&pV, g_V);
    cudaGetSymbolAddress(&pS, g_S);
    float* Q = (float*)pQ;
    float* K = (float*)pK;
    float* V = (float*)pV;
    float* S = (float*)pS;

    const int M_qkv = BATCH * SEQ;   // 16384
    dim3 block(256);

    // dynamic smem sizes (3 stages)
    const int smemNN = 3 * (128 * 36 + 32 * 132) * 4;   // 105984 B
    const int smemNT = 3 * (128 * 36 + 128 * 36) * 4;   // 110592 B

    cudaFuncSetAttribute(gemm_tf32_kernel<false, true>,
                         cudaFuncAttributeMaxDynamicSharedMemorySize, smemNN);
    cudaFuncSetAttribute(gemm_tf32_kernel<false, false>,
                         cudaFuncAttributeMaxDynamicSharedMemorySize, smemNN);
    cudaFuncSetAttribute(gemm_tf32_kernel<true, false>,
                         cudaFuncAttributeMaxDynamicSharedMemorySize, smemNT);

    // 1) QKV projections: relu(X @ W + b), NN, M=16384 N=1024 K=1024
    {
        dim3 grid(DIM / 128, M_qkv / 128, 1);
        gemm_tf32_kernel<false, true><<<grid, block, smemNN>>>(X, Wq, bq, Q, M_qkv, DIM, DIM, 0, 0, 0);
        gemm_tf32_kernel<false, true><<<grid, block, smemNN>>>(X, Wk, bk, K, M_qkv, DIM, DIM, 0, 0, 0);
        gemm_tf32_kernel<false, true><<<grid, block, smemNN>>>(X, Wv, bv, V, M_qkv, DIM, DIM, 0, 0, 0);
    }

    // 2) scores: S_b = Q_b @ K_b^T, per-batch, M=N=2048 K=1024 (NT)
    {
        dim3 grid(SEQ / 128, SEQ / 128, BATCH);
        gemm_tf32_kernel<true, false><<<grid, block, smemNT>>>(
            Q, K, nullptr, S, SEQ, SEQ, DIM,
            (size_t)SEQ * DIM, (size_t)SEQ * DIM, (size_t)SEQ * SEQ);
    }

    // 3) softmax over rows of S
    softmax_kernel<<<BATCH * SEQ, 256>>>(S, SEQ);

    // 4) out: O_b = P_b @ V_b, M=2048 N=1024 K=2048 (NN)
    {
        dim3 grid(DIM / 128, SEQ / 128, BATCH);
        gemm_tf32_kernel<false, false><<<grid, block, smemNN>>>(
            S, V, nullptr, out, SEQ, DIM, SEQ,
            (size_t)SEQ * SEQ, (size_t)SEQ * DIM, (size_t)SEQ * DIM);
    }
}

// round 4
// speedup vs baseline: 1.2282x; 1.1459x over previous
#include <cuda_runtime.h>
#include <cstdint>

// ---------------------------------------------------------------------------
// SelfAttention: O = softmax( relu(XWq+bq) @ relu(XWk+bk)^T ) @ relu(XWv+bv)
// B=8, T=2048, D=DK=DV=1024, fp32 in/out.
// tf32 mma.sync NT GEMMs, 64x64 warp tiles, 3-stage cp.async pipeline.
// All tensor-core inputs pre-rounded to tf32 (cvt.rna) in HBM -> zero inner cvts.
// ---------------------------------------------------------------------------

#define BATCH 8
#define SEQ   2048
#define DIM   1024

// Scratch (device globals; no allocations allowed)
__device__ __align__(1024) float g_X [(size_t)BATCH * SEQ * DIM];
__device__ __align__(1024) float g_Q [(size_t)BATCH * SEQ * DIM];
__device__ __align__(1024) float g_K [(size_t)BATCH * SEQ * DIM];
__device__ __align__(1024) float g_V [(size_t)BATCH * SEQ * DIM];
__device__ __align__(1024) float g_Vt[(size_t)BATCH * SEQ * DIM];
__device__ __align__(1024) float g_S [(size_t)BATCH * SEQ * SEQ];
__device__ __align__(1024) float g_Wt[(size_t)DIM * DIM];

__device__ __forceinline__ uint32_t f2tf32(float x) {
    uint32_t y;
    asm("cvt.rna.tf32.f32 %0, %1;" : "=r"(y) : "f"(x));
    return y;
}

__device__ __forceinline__ void mma_tf32(float c[4], const uint32_t a[4], const uint32_t b[2]) {
    asm volatile(
        "mma.sync.aligned.m16n8k8.row.col.f32.tf32.tf32.f32 "
        "{%0,%1,%2,%3}, {%4,%5,%6,%7}, {%8,%9}, {%0,%1,%2,%3};"
        : "+f"(c[0]), "+f"(c[1]), "+f"(c[2]), "+f"(c[3])
        : "r"(a[0]), "r"(a[1]), "r"(a[2]), "r"(a[3]), "r"(b[0]), "r"(b[1]));
}

__device__ __forceinline__ void cp_async16(void* smem_dst, const void* gsrc) {
    uint32_t d = (uint32_t)__cvta_generic_to_shared(smem_dst);
    asm volatile("cp.async.cg.shared.global [%0], [%1], 16;\n" :: "r"(d), "l"(gsrc));
}
__device__ __forceinline__ void cp_commit() {
    asm volatile("cp.async.commit_group;\n" ::: "memory");
}
template <int N>
__device__ __forceinline__ void cp_wait() {
    asm volatile("cp.async.wait_group %0;\n" :: "n"(N) : "memory");
}

// ---------------------------------------------------------------------------
// NT tf32 GEMM: C[M,N] = A[M,K] @ B[N,K]^T  (both row-major / K-major).
// Inputs must already be tf32-rounded bit patterns.
// Block 128x128x32, 128 threads (4 warps), warp tile 64x64, 3-stage cp.async.
// Batched via blockIdx.z with element strides.
// ---------------------------------------------------------------------------
template <bool BIAS_RELU, bool ROUND_OUT>
__global__ __launch_bounds__(128, 2)
void gemm_nt_kernel(const float* __restrict__ A, const float* __restrict__ B,
                    const float* __restrict__ bias, float* __restrict__ C,
                    int M, int N, int K,
                    size_t strideA, size_t strideB, size_t strideC)
{
    constexpr int BK = 32, STAGES = 3;
    constexpr int ST  = 36;                 // padded row stride (floats)
    constexpr int TSZ = 128 * ST;           // one tile (A or B) in floats

    extern __shared__ float sm[];           // [STAGES][A tile + B tile]

    A += (size_t)blockIdx.z * strideA;
    B += (size_t)blockIdx.z * strideB;
    C += (size_t)blockIdx.z * strideC;

    const int tid  = threadIdx.x;
    const int lane = tid & 31;
    const int warp = tid >> 5;
    const int wm0  = (warp >> 1) * 64;      // 2x2 warp grid
    const int wn0  = (warp & 1) * 64;

    const int blockM = blockIdx.y * 128;
    const int blockN = blockIdx.x * 128;

    const int qr = lane >> 2;   // 0..7
    const int qc = lane & 3;    // 0..3

    float acc[4][8][4];
    #pragma unroll
    for (int i = 0; i < 4; i++)
        #pragma unroll
        for (int j = 0; j < 8; j++)
            #pragma unroll
            for (int v = 0; v < 4; v++) acc[i][j][v] = 0.0f;

    // ---- async tile loader: A tile 128xBK and B tile 128xBK ----
    auto load_tile = [&](int stage, int k0) {
        float* Asd = sm + stage * (2 * TSZ);
        float* Bsd = Asd + TSZ;
        const float* Ag = A + (size_t)blockM * K + k0;
        const float* Bg = B + (size_t)blockN * K + k0;
        #pragma unroll
        for (int p = 0; p < 8; p++) {
            int idx = tid + p * 128;        // 1024 chunks of 16B per tile
            int r   = idx >> 3;
            int c4  = idx & 7;
            cp_async16(Asd + r * ST + c4 * 4, Ag + (size_t)r * K + c4 * 4);
            cp_async16(Bsd + r * ST + c4 * 4, Bg + (size_t)r * K + c4 * 4);
        }
    };

    const int KT = K / BK;

    load_tile(0, 0);   cp_commit();
    load_tile(1, BK);  cp_commit();

    for (int kt = 0; kt < KT; kt++) {
        cp_wait<1>();
        __syncthreads();

        if (kt + 2 < KT) load_tile((kt + 2) % STAGES, (kt + 2) * BK);
        cp_commit();

        const float* Asb = sm + (kt % STAGES) * (2 * TSZ);
        const float* Bsb = Asb + TSZ;
        const uint32_t* Asu = (const uint32_t*)Asb;
        const uint32_t* Bsu = (const uint32_t*)Bsb;

        #pragma unroll
        for (int kk = 0; kk < BK; kk += 8) {
            uint32_t a[4][4];
            #pragma unroll
            for (int mt = 0; mt < 4; mt++) {
                int r0 = wm0 + mt * 16 + qr;
                a[mt][0] = Asu[r0 * ST + kk + qc];
                a[mt][1] = Asu[(r0 + 8) * ST + kk + qc];
                a[mt][2] = Asu[r0 * ST + kk + qc + 4];
                a[mt][3] = Asu[(r0 + 8) * ST + kk + qc + 4];
            }
            uint32_t b[8][2];
            #pragma unroll
            for (int nt = 0; nt < 8; nt++) {
                int n = wn0 + nt * 8 + qr;
                b[nt][0] = Bsu[n * ST + kk + qc];
                b[nt][1] = Bsu[n * ST + kk + qc + 4];
            }
            #pragma unroll
            for (int mt = 0; mt < 4; mt++)
                #pragma unroll
                for (int nt = 0; nt < 8; nt++)
                    mma_tf32(acc[mt][nt], a[mt], b[nt]);
        }
    }

    // ---- epilogue ----
    #pragma unroll
    for (int mt = 0; mt < 4; mt++) {
        #pragma unroll
        for (int nt = 0; nt < 8; nt++) {
            int gm = blockM + wm0 + mt * 16 + qr;
            int gn = blockN + wn0 + nt * 8 + qc * 2;
            float2 v0, v1;
            v0.x = acc[mt][nt][0]; v0.y = acc[mt][nt][1];
            v1.x = acc[mt][nt][2]; v1.y = acc[mt][nt][3];
            if (BIAS_RELU) {
                float2 bb = *reinterpret_cast<const float2*>(&bias[gn]);
                v0.x = fmaxf(v0.x + bb.x, 0.0f);
                v0.y = fmaxf(v0.y + bb.y, 0.0f);
                v1.x = fmaxf(v1.x + bb.x, 0.0f);
                v1.y = fmaxf(v1.y + bb.y, 0.0f);
            }
            if (ROUND_OUT) {
                v0.x = __uint_as_float(f2tf32(v0.x));
                v0.y = __uint_as_float(f2tf32(v0.y));
                v1.x = __uint_as_float(f2tf32(v1.x));
                v1.y = __uint_as_float(f2tf32(v1.y));
            }
            *reinterpret_cast<float2*>(&C[(size_t)gm * N + gn]) = v0;
            *reinterpret_cast<float2*>(&C[(size_t)(gm + 8) * N + gn]) = v1;
        }
    }
}

// ---------------------------------------------------------------------------
// tf32-round copy (for X)
// ---------------------------------------------------------------------------
__global__ __launch_bounds__(256)
void cvt_tf32_kernel(const float4* __restrict__ in, float4* __restrict__ out, int n4)
{
    int i = blockIdx.x * 256 + threadIdx.x;
    if (i < n4) {
        float4 t = in[i];
        float4 o;
        o.x = __uint_as_float(f2tf32(t.x));
        o.y = __uint_as_float(f2tf32(t.y));
        o.z = __uint_as_float(f2tf32(t.z));
        o.w = __uint_as_float(f2tf32(t.w));
        out[i] = o;
    }
}

// ---------------------------------------------------------------------------
// Tiled transpose: out[c][r] = in[r][c] (optionally tf32-rounded), batched.
// ---------------------------------------------------------------------------
template <bool CVT>
__global__ __launch_bounds__(256)
void transpose_kernel(const float* __restrict__ in, float* __restrict__ out,
                      int R, int C, size_t strideIn, size_t strideOut)
{
    __shared__ float t[32][33];
    in  += (size_t)blockIdx.z * strideIn;
    out += (size_t)blockIdx.z * strideOut;

    const int tx = threadIdx.x, ty = threadIdx.y;
    const int c0 = blockIdx.x * 32;
    const int r0 = blockIdx.y * 32;

    #pragma unroll
    for (int j = 0; j < 32; j += 8)
        t[ty + j][tx] = in[(size_t)(r0 + ty + j) * C + c0 + tx];
    __syncthreads();
    #pragma unroll
    for (int j = 0; j < 32; j += 8) {
        float v = t[tx][ty + j];
        if (CVT) v = __uint_as_float(f2tf32(v));
        out[(size_t)(c0 + ty + j) * R + r0 + tx] = v;
    }
}

// ---------------------------------------------------------------------------
// Row softmax over rows of length 2048; output tf32-rounded (feeds PV GEMM).
// ---------------------------------------------------------------------------
__global__ __launch_bounds__(256)
void softmax_kernel(float* __restrict__ S, int ncols)
{
    const size_t row = blockIdx.x;
    float* p = S + row * (size_t)ncols;
    const int tid  = threadIdx.x;
    const int lane = tid & 31;
    const int warp = tid >> 5;

    __shared__ float red[8];

    float v[8];
    float m = -1e30f;
    #pragma unroll
    for (int i = 0; i < 8; i++) {
        v[i] = p[tid + i * 256];
        m = fmaxf(m, v[i]);
    }
    #pragma unroll
    for (int o = 16; o; o >>= 1) m = fmaxf(m, __shfl_xor_sync(0xffffffffu, m, o));
    if (lane == 0) red[warp] = m;
    __syncthreads();
    m = red[0];
    #pragma unroll
    for (int i = 1; i < 8; i++) m = fmaxf(m, red[i]);
    __syncthreads();

    float s = 0.0f;
    #pragma unroll
    for (int i = 0; i < 8; i++) {
        v[i] = __expf(v[i] - m);
        s += v[i];
    }
    #pragma unroll
    for (int o = 16; o; o >>= 1) s += __shfl_xor_sync(0xffffffffu, s, o);
    if (lane == 0) red[warp] = s;
    __syncthreads();
    float tot = red[0];
    #pragma unroll
    for (int i = 1; i < 8; i++) tot += red[i];
    float inv = 1.0f / tot;
    #pragma unroll
    for (int i = 0; i < 8; i++)
        p[tid + i * 256] = __uint_as_float(f2tf32(v[i] * inv));
}

// ---------------------------------------------------------------------------
// Launch
// ---------------------------------------------------------------------------
extern "C" void kernel_launch(void* const* d_in, const int* in_sizes, int n_in,
                              void* d_out, int out_size)
{
    const float* X  = (const float*)d_in[0];
    const float* Wq = (const float*)d_in[1];
    const float* bq = (const float*)d_in[2];
    const float* Wk = (const float*)d_in[3];
    const float* bk = (const float*)d_in[4];
    const float* Wv = (const float*)d_in[5];
    const float* bv = (const float*)d_in[6];
    float* out = (float*)d_out;

    void *pX, *pQ, *pK, *pV, *pVt, *pS, *pWt;
    cudaGetSymbolAddress(&pX,  g_X);
    cudaGetSymbolAddress(&pQ,  g_Q);
    cudaGetSymbolAddress(&pK,  g_K);
    cudaGetSymbolAddress(&pV,  g_V);
    cudaGetSymbolAddress(&pVt, g_Vt);
    cudaGetSymbolAddress(&pS,  g_S);
    cudaGetSymbolAddress(&pWt, g_Wt);
    float* Xc = (float*)pX;
    float* Q  = (float*)pQ;
    float* Kp = (float*)pK;
    float* V  = (float*)pV;
    float* Vt = (float*)pVt;
    float* S  = (float*)pS;
    float* Wt = (float*)pWt;

    const int M_qkv = BATCH * SEQ;                 // 16384
    const int SMEM  = 3 * 2 * 128 * 36 * 4;        // 110592 B

    cudaFuncSetAttribute(gemm_nt_kernel<true,  true>,
                         cudaFuncAttributeMaxDynamicSharedMemorySize, SMEM);
    cudaFuncSetAttribute(gemm_nt_kernel<false, false>,
                         cudaFuncAttributeMaxDynamicSharedMemorySize, SMEM);

    // 0) X -> tf32-rounded copy
    {
        int n4 = M_qkv * DIM / 4;
        cvt_tf32_kernel<<<(n4 + 255) / 256, 256>>>((const float4*)X, (float4*)Xc, n4);
    }

    dim3 tb(32, 8);

    // 1) QKV projections: relu(X @ W + b) via NT GEMM with W^T (tf32-rounded)
    {
        dim3 tg(DIM / 32, DIM / 32, 1);
        dim3 gg(DIM / 128, M_qkv / 128, 1);
        transpose_kernel<true><<<tg, tb>>>(Wq, Wt, DIM, DIM, 0, 0);
        gemm_nt_kernel<true, true><<<gg, 128, SMEM>>>(Xc, Wt, bq, Q, M_qkv, DIM, DIM, 0, 0, 0);
        transpose_kernel<true><<<tg, tb>>>(Wk, Wt, DIM, DIM, 0, 0);
        gemm_nt_kernel<true, true><<<gg, 128, SMEM>>>(Xc, Wt, bk, Kp, M_qkv, DIM, DIM, 0, 0, 0);
        transpose_kernel<true><<<tg, tb>>>(Wv, Wt, DIM, DIM, 0, 0);
        gemm_nt_kernel<true, true><<<gg, 128, SMEM>>>(Xc, Wt, bv, V, M_qkv, DIM, DIM, 0, 0, 0);
    }

    // 2) scores: S_b = Q_b @ K_b^T (NT, native), fp32 out
    {
        dim3 gg(SEQ / 128, SEQ / 128, BATCH);
        gemm_nt_kernel<false, false><<<gg, 128, SMEM>>>(
            Q, Kp, nullptr, S, SEQ, SEQ, DIM,
            (size_t)SEQ * DIM, (size_t)SEQ * DIM, (size_t)SEQ * SEQ);
    }

    // 3) softmax (tf32-rounded output)
    softmax_kernel<<<BATCH * SEQ, 256>>>(S, SEQ);

    // 4) V^T per batch, then O_b = P_b @ (V_b^T)^T (NT)
    {
        dim3 tg(DIM / 32, SEQ / 32, BATCH);
        transpose_kernel<false><<<tg, tb>>>(V, Vt, SEQ, DIM,
                                            (size_t)SEQ * DIM, (size_t)SEQ * DIM);
        dim3 gg(DIM / 128, SEQ / 128, BATCH);
        gemm_nt_kernel<false, false><<<gg, 128, SMEM>>>(
            S, Vt, nullptr, out, SEQ, DIM, SEQ,
            (size_t)SEQ * SEQ, (size_t)SEQ * DIM, (size_t)SEQ * DIM);
    }
}